// round 13
// baseline (speedup 1.0000x reference)
#include <cuda_runtime.h>
#include <cstdint>

// Problem constants
#define B_     16
#define L_     1024
#define D_     256
#define PAST_  16
#define LQ_    (L_ - PAST_)   // 1008
#define NL_    3

#define O_ELEMS   ((size_t)B_ * LQ_ * 256)   // 4,128,768 floats

// ---- scratch (__device__ arrays: no cudaMalloc allowed) ----
__device__ float g_P[(size_t)B_ * L_ * 256];   // P = inp @ W^T over ALL rows (16.7 MB)
__device__ float g_w[(size_t)B_ * L_ * 8];     // 8 effective lookback weights per (b,l)

__device__ __forceinline__ unsigned f2tf32(float x) {
    unsigned u;
    asm("cvt.rna.tf32.f32 %0, %1;" : "=r"(u) : "f"(x));
    return u;
}

__device__ __forceinline__ void mma_tf32(float* c, const unsigned* a, const unsigned* b) {
    asm volatile(
        "mma.sync.aligned.m16n8k8.row.col.f32.tf32.tf32.f32 "
        "{%0,%1,%2,%3}, {%4,%5,%6,%7}, {%8,%9}, {%0,%1,%2,%3};"
        : "+f"(c[0]), "+f"(c[1]), "+f"(c[2]), "+f"(c[3])
        : "r"(a[0]), "r"(a[1]), "r"(a[2]), "r"(a[3]), "r"(b[0]), "r"(b[1]));
}

// =====================================================================
// attention-chain helpers (proven numerics — do not alter)
// =====================================================================
__device__ __forceinline__ void load_row8(float* x, const float* base, int r, int c)
{
    if (r >= 0) {
        float4 v0 = *(const float4*)(base + (size_t)r * D_ + c);
        float4 v1 = *(const float4*)(base + (size_t)r * D_ + c + 4);
        x[0]=v0.x; x[1]=v0.y; x[2]=v0.z; x[3]=v0.w;
        x[4]=v1.x; x[5]=v1.y; x[6]=v1.z; x[7]=v1.w;
    } else {
        #pragma unroll
        for (int k = 0; k < 8; k++) x[k] = 0.f;
    }
}

__device__ __forceinline__ void dot2(const float* u, const float* v, float& p0, float& p1)
{
    float s0 = 0.f, s1 = 0.f;
    #pragma unroll
    for (int k = 0; k < 8; k++) {
        s0 = fmaf(u[k], u[k], s0);
        s1 = fmaf(u[k], v[k], s1);
    }
    #pragma unroll
    for (int o = 16; o; o >>= 1) {
        s0 += __shfl_xor_sync(0xffffffffu, s0, o);
        s1 += __shfl_xor_sync(0xffffffffu, s1, o);
    }
    p0 = s0; p1 = s1;
}

__device__ __forceinline__ void coef2(float p0, float p1, bool valid, float& a0, float& a1)
{
    if (valid) {
        float s0 = p0 * 0.0625f;   // 1/sqrt(256)
        float s1 = p1 * 0.0625f;
        float m  = fmaxf(s0, s1);
        float e0 = expf(s0 - m);
        float e1 = expf(s1 - m);
        float inv = 1.f / (e0 + e1);
        a0 = e0 * inv;
        a1 = e1 * inv;
    } else {
        a0 = 1.f; a1 = 0.f;
    }
}

// =====================================================================
// Kernel A (branch 1, s2): attn fill ONLY. One warp per (b,l):
// chain coefs -> 3 attn rows. No w, no mid.
// =====================================================================
__global__ void __launch_bounds__(256)
fill_kernel(const float* __restrict__ inp, float* __restrict__ attn_out)
{
    const int lane = threadIdx.x & 31;
    const int row  = blockIdx.x * 8 + (threadIdx.x >> 5);   // 0..16383
    const int b    = row >> 10;
    const int l    = row & (L_ - 1);
    const float* base = inp + (size_t)b * L_ * D_;
    const int c = lane * 8;

    float A0[NL_], A1[NL_];

    float o1[4][8];
    #pragma unroll
    for (int t = 0; t < 4; t++) {
        int lh = l - 2 * t;
        float xh[8], xl[8];
        load_row8(xh, base, lh, c);
        load_row8(xl, base, lh - 1, c);
        float p0, p1; dot2(xh, xl, p0, p1);
        float b0, b1; coef2(p0, p1, lh >= 1, b0, b1);
        #pragma unroll
        for (int k = 0; k < 8; k++)
            o1[t][k] = fmaf(b0, xh[k], fmaf(b1, xl[k], xh[k]));
        if (t == 0) { A0[0] = b0; A1[0] = b1; }
    }
    float o2[2][8];
    #pragma unroll
    for (int t = 0; t < 2; t++) {
        int lh = l - 4 * t;
        float p0, p1; dot2(o1[2 * t], o1[2 * t + 1], p0, p1);
        float b0, b1; coef2(p0, p1, lh >= 2, b0, b1);
        #pragma unroll
        for (int k = 0; k < 8; k++)
            o2[t][k] = fmaf(b0, o1[2 * t][k], fmaf(b1, o1[2 * t + 1][k], o1[2 * t][k]));
        if (t == 0) { A0[1] = b0; A1[1] = b1; }
    }
    {
        float p0, p1; dot2(o2[0], o2[1], p0, p1);
        float c0, c1; coef2(p0, p1, l >= 4, c0, c1);
        A0[2] = c0; A1[2] = c1;
    }

    #pragma unroll
    for (int layer = 0; layer < NL_; layer++) {
        const int d  = 1 << layer;
        const int c0 = l;
        const int c1 = l - d;
        const float a0 = A0[layer];
        const float a1 = A1[layer];
        float4* dst = (float4*)(attn_out + ((size_t)(b * NL_ + layer) * L_ + l) * L_);
        #pragma unroll
        for (int s = 0; s < 8; s++) {
            int q = lane + (s << 5);
            float4 v = make_float4(0.f, 0.f, 0.f, 0.f);
            if ((c0 >> 2) == q)              ((float*)&v)[c0 & 3] = a0;
            if (c1 >= 0 && (c1 >> 2) == q)   ((float*)&v)[c1 & 3] = a1;
            __stcs(dst + q, v);
        }
    }
}

// =====================================================================
// Kernel B (branch 2, s3): P = inp @ W^T over all 16384 rows
// + (n-block 0 only) w-weights epilogue for its 128 rows.
// =====================================================================
#define GBM 128
#define GBN 128
#define GBK 32
#define SST 36

__global__ void __launch_bounds__(256, 2)
gemmP_w_kernel(const float* __restrict__ inp, const float* __restrict__ W)
{
    __shared__ unsigned As[GBM * SST];
    __shared__ unsigned Bs[GBN * SST];

    const int tid  = threadIdx.x;
    const int m0   = blockIdx.x * GBM;
    const int n0   = blockIdx.y * GBN;
    const int wid  = tid >> 5;
    const int lane = tid & 31;
    const int warp_m = wid & 3;
    const int warp_n = wid >> 2;
    const int gid = lane >> 2;
    const int tig = lane & 3;

    float acc[2][8][4];
    #pragma unroll
    for (int i = 0; i < 2; i++)
        #pragma unroll
        for (int j = 0; j < 8; j++)
            #pragma unroll
            for (int k = 0; k < 4; k++) acc[i][j][k] = 0.f;

    const float* aPtr[4];
    const float* bPtr[4];
    int sOff[4];
    #pragma unroll
    for (int it = 0; it < 4; it++) {
        int idx = tid + it * 256;
        int r   = idx >> 3;
        int q   = idx & 7;
        aPtr[it] = inp + (size_t)(m0 + r) * 256 + q * 4;
        bPtr[it] = W + (size_t)(n0 + r) * 256 + q * 4;
        sOff[it] = r * SST + q * 4;
    }

    float4 aR[4], bR[4];
    #pragma unroll
    for (int it = 0; it < 4; it++) {
        aR[it] = *(const float4*)(aPtr[it]);
        bR[it] = *(const float4*)(bPtr[it]);
    }

    #pragma unroll
    for (int i = 0; i < 8; i++) {
        const int kc = i * GBK;
        __syncthreads();
        #pragma unroll
        for (int it = 0; it < 4; it++) {
            *(uint4*)(As + sOff[it]) =
                make_uint4(f2tf32(aR[it].x), f2tf32(aR[it].y), f2tf32(aR[it].z), f2tf32(aR[it].w));
            *(uint4*)(Bs + sOff[it]) =
                make_uint4(f2tf32(bR[it].x), f2tf32(bR[it].y), f2tf32(bR[it].z), f2tf32(bR[it].w));
        }
        __syncthreads();

        if (i < 7) {
            #pragma unroll
            for (int it = 0; it < 4; it++) {
                aR[it] = *(const float4*)(aPtr[it] + kc + GBK);
                bR[it] = *(const float4*)(bPtr[it] + kc + GBK);
            }
        }

        #pragma unroll
        for (int kk = 0; kk < GBK; kk += 8) {
            unsigned a[2][4], bq[8][2];
            #pragma unroll
            for (int mt = 0; mt < 2; mt++) {
                int r = warp_m * 32 + mt * 16 + gid;
                a[mt][0] = As[r * SST + kk + tig];
                a[mt][1] = As[(r + 8) * SST + kk + tig];
                a[mt][2] = As[r * SST + kk + tig + 4];
                a[mt][3] = As[(r + 8) * SST + kk + tig + 4];
            }
            #pragma unroll
            for (int nt = 0; nt < 8; nt++) {
                int cix = warp_n * 64 + nt * 8 + gid;
                bq[nt][0] = Bs[cix * SST + kk + tig];
                bq[nt][1] = Bs[cix * SST + kk + tig + 4];
            }
            #pragma unroll
            for (int mt = 0; mt < 2; mt++)
                #pragma unroll
                for (int nt = 0; nt < 8; nt++)
                    mma_tf32(acc[mt][nt], a[mt], bq[nt]);
        }
    }

    // write P tile
    #pragma unroll
    for (int mt = 0; mt < 2; mt++) {
        #pragma unroll
        for (int half = 0; half < 2; half++) {
            int m = m0 + warp_m * 32 + mt * 16 + gid + half * 8;
            float* prow = g_P + (size_t)m * 256;
            #pragma unroll
            for (int nt = 0; nt < 8; nt++) {
                int col = n0 + warp_n * 64 + nt * 8 + 2 * tig;
                *(float2*)(prow + col) =
                    make_float2(acc[mt][nt][half * 2 + 0], acc[mt][nt][half * 2 + 1]);
            }
        }
    }

    // ---- w epilogue (n-block 0 only): chain per row, one warp per row ----
    if (n0 != 0) return;

    const int c8 = lane * 8;
    for (int r = wid; r < GBM; r += 8) {
        const int row = m0 + r;            // global (b,l) index
        const int b   = row >> 10;
        const int l   = row & (L_ - 1);
        const float* base = inp + (size_t)b * L_ * D_;

        float al0[4], al1[4];
        float g0, d0, g1, d1;

        float o1[4][8];
        #pragma unroll
        for (int t = 0; t < 4; t++) {
            int lh = l - 2 * t;
            float xh[8], xl[8];
            load_row8(xh, base, lh, c8);
            load_row8(xl, base, lh - 1, c8);
            float p0, p1; dot2(xh, xl, p0, p1);
            float b0, b1; coef2(p0, p1, lh >= 1, b0, b1);
            al0[t] = b0; al1[t] = b1;
            #pragma unroll
            for (int k = 0; k < 8; k++)
                o1[t][k] = fmaf(b0, xh[k], fmaf(b1, xl[k], xh[k]));
        }
        float o2[2][8];
        #pragma unroll
        for (int t = 0; t < 2; t++) {
            int lh = l - 4 * t;
            float p0, p1; dot2(o1[2 * t], o1[2 * t + 1], p0, p1);
            float b0, b1; coef2(p0, p1, lh >= 2, b0, b1);
            if (t == 0) { g0 = b0; d0 = b1; }
            else        { g1 = b0; d1 = b1; }
            #pragma unroll
            for (int k = 0; k < 8; k++)
                o2[t][k] = fmaf(b0, o1[2 * t][k], fmaf(b1, o1[2 * t + 1][k], o1[2 * t][k]));
        }
        float e0, z0;
        {
            float p0, p1; dot2(o2[0], o2[1], p0, p1);
            coef2(p0, p1, l >= 4, e0, z0);
        }

        if (lane == 0) {
            float eps = 1.f + e0, zet = z0;
            float G0 = 1.f + g0, D0v = d0, G1 = 1.f + g1, D1v = d1;
            float w0 = eps * G0  * (1.f + al0[0]);
            float w1 = eps * G0  * al1[0];
            float w2 = eps * D0v * (1.f + al0[1]);
            float w3 = eps * D0v * al1[1];
            float w4 = zet * G1  * (1.f + al0[2]);
            float w5 = zet * G1  * al1[2];
            float w6 = zet * D1v * (1.f + al0[3]);
            float w7 = zet * D1v * al1[3];
            float* wp = g_w + (size_t)row * 8;
            *(float4*)(wp)     = make_float4(w0, w1, w2, w3);
            *(float4*)(wp + 4) = make_float4(w4, w5, w6, w7);
        }
    }
}

// =====================================================================
// Kernel C (s3, after gemmP): o = sum_j w_j * P[l-j] + bias + residual
// (round-9 proven)
// =====================================================================
#define RPT 4

__global__ void __launch_bounds__(256)
combine_kernel(const float* __restrict__ inp, const float* __restrict__ bias,
               float* __restrict__ o_out)
{
    const int tid  = threadIdx.x;
    const int grp  = blockIdx.x * 4 + (tid >> 6);
    const int colq = tid & 63;
    const int col  = colq * 4;

    const int mb   = grp * RPT;
    const int b    = mb / LQ_;
    const int lq0  = mb - b * LQ_;
    const int l0   = lq0 + PAST_;

    const float4 bi = *(const float4*)(bias + col);
    const float* pbase = g_P + ((size_t)b * L_) * 256 + col;
    const float* wbase = g_w + ((size_t)b * L_ + l0) * 8;
    const float* rbase = inp + ((size_t)b * L_ + l0) * D_ + (col & 63);
    float* obase = o_out + (size_t)mb * 256 + col;

    float4 p[8];
    #pragma unroll
    for (int i = 0; i < 8; i++)
        p[i] = *(const float4*)(pbase + (size_t)(l0 - 7 + i) * 256);

    #pragma unroll
    for (int r = 0; r < RPT; r++) {
        const float4 w0 = *(const float4*)(wbase + r * 8);
        const float4 w1 = *(const float4*)(wbase + r * 8 + 4);
        const float4 rv = *(const float4*)(rbase + (size_t)r * D_);

        float4 acc;
        acc.x = bi.x + rv.x; acc.y = bi.y + rv.y;
        acc.z = bi.z + rv.z; acc.w = bi.w + rv.w;
        const float wj[8] = { w0.x, w0.y, w0.z, w0.w, w1.x, w1.y, w1.z, w1.w };
        #pragma unroll
        for (int j = 0; j < 8; j++) {
            const float4 pv = p[7 - j];
            acc.x = fmaf(wj[j], pv.x, acc.x);
            acc.y = fmaf(wj[j], pv.y, acc.y);
            acc.z = fmaf(wj[j], pv.z, acc.z);
            acc.w = fmaf(wj[j], pv.w, acc.w);
        }
        __stcs((float4*)(obase + (size_t)r * 256), acc);

        if (r < RPT - 1) {
            #pragma unroll
            for (int i = 0; i < 7; i++) p[i] = p[i + 1];
            p[7] = *(const float4*)(pbase + (size_t)(l0 + r + 1) * 256);
        }
    }
}

// =====================================================================
// launch: s3 (HIGH priority): gemmP_w -> combine ;  s2: fill.
// gemmP recorded FIRST so its CTAs claim SM residency at replay.
// =====================================================================
static cudaStream_t g_s2 = 0, g_s3 = 0;
static cudaEvent_t  g_fork = 0, g_j2 = 0, g_j3 = 0;
static struct StreamInit {
    StreamInit() {
        int lo = 0, hi = 0;
        cudaDeviceGetStreamPriorityRange(&lo, &hi);   // hi = greatest priority
        cudaStreamCreateWithPriority(&g_s3, cudaStreamNonBlocking, hi);
        cudaStreamCreateWithPriority(&g_s2, cudaStreamNonBlocking, lo);
        cudaEventCreateWithFlags(&g_fork, cudaEventDisableTiming);
        cudaEventCreateWithFlags(&g_j2, cudaEventDisableTiming);
        cudaEventCreateWithFlags(&g_j3, cudaEventDisableTiming);
    }
} g_stream_init;

extern "C" void kernel_launch(void* const* d_in, const int* in_sizes, int n_in,
                              void* d_out, int out_size)
{
    const float* inp  = (const float*)d_in[0];
    const float* W    = (const float*)d_in[1];
    const float* bias = (const float*)d_in[2];
    // d_in[3] = masks : compile-time structure, unused

    float* out  = (float*)d_out;           // o : (16, 1008, 4, 64)
    float* attn = out + O_ELEMS;           // attn_stack : (16, 3, 1024, 1024)

    cudaEventRecord(g_fork, 0);
    cudaStreamWaitEvent(g_s3, g_fork, 0);
    cudaStreamWaitEvent(g_s2, g_fork, 0);

    // gemm first (residency priority), then fill backfills
    gemmP_w_kernel<<<dim3((B_ * L_) / GBM, 256 / GBN), 256, 0, g_s3>>>(inp, W);
    fill_kernel<<<(B_ * L_) / 8, 256, 0, g_s2>>>(inp, attn);

    // combine depends only on s3 (P and w both produced there)
    combine_kernel<<<(B_ * LQ_ / RPT) / 4, 256, 0, g_s3>>>(inp, bias, out);

    cudaEventRecord(g_j2, g_s2);
    cudaEventRecord(g_j3, g_s3);
    cudaStreamWaitEvent(0, g_j2, 0);
    cudaStreamWaitEvent(0, g_j3, 0);
}

// round 14
// speedup vs baseline: 1.0822x; 1.0822x over previous
#include <cuda_runtime.h>
#include <cstdint>

// Problem constants
#define B_     16
#define L_     1024
#define D_     256
#define PAST_  16
#define LQ_    (L_ - PAST_)   // 1008
#define NL_    3

#define O_ELEMS   ((size_t)B_ * LQ_ * 256)   // 4,128,768 floats

// ---- scratch (__device__ array: no cudaMalloc allowed) ----
__device__ float g_P[(size_t)B_ * L_ * 256];   // P = inp @ W^T over ALL rows (16.7 MB)

__device__ __forceinline__ unsigned f2tf32(float x) {
    unsigned u;
    asm("cvt.rna.tf32.f32 %0, %1;" : "=r"(u) : "f"(x));
    return u;
}

__device__ __forceinline__ void mma_tf32(float* c, const unsigned* a, const unsigned* b) {
    asm volatile(
        "mma.sync.aligned.m16n8k8.row.col.f32.tf32.tf32.f32 "
        "{%0,%1,%2,%3}, {%4,%5,%6,%7}, {%8,%9}, {%0,%1,%2,%3};"
        : "+f"(c[0]), "+f"(c[1]), "+f"(c[2]), "+f"(c[3])
        : "r"(a[0]), "r"(a[1]), "r"(a[2]), "r"(a[3]), "r"(b[0]), "r"(b[1]));
}

// =====================================================================
// attention-chain helpers (proven numerics — do not alter)
// =====================================================================
__device__ __forceinline__ void load_row8(float* x, const float* base, int r, int c)
{
    if (r >= 0) {
        float4 v0 = *(const float4*)(base + (size_t)r * D_ + c);
        float4 v1 = *(const float4*)(base + (size_t)r * D_ + c + 4);
        x[0]=v0.x; x[1]=v0.y; x[2]=v0.z; x[3]=v0.w;
        x[4]=v1.x; x[5]=v1.y; x[6]=v1.z; x[7]=v1.w;
    } else {
        #pragma unroll
        for (int k = 0; k < 8; k++) x[k] = 0.f;
    }
}

__device__ __forceinline__ void dot2(const float* u, const float* v, float& p0, float& p1)
{
    float s0 = 0.f, s1 = 0.f;
    #pragma unroll
    for (int k = 0; k < 8; k++) {
        s0 = fmaf(u[k], u[k], s0);
        s1 = fmaf(u[k], v[k], s1);
    }
    #pragma unroll
    for (int o = 16; o; o >>= 1) {
        s0 += __shfl_xor_sync(0xffffffffu, s0, o);
        s1 += __shfl_xor_sync(0xffffffffu, s1, o);
    }
    p0 = s0; p1 = s1;
}

__device__ __forceinline__ void coef2(float p0, float p1, bool valid, float& a0, float& a1)
{
    if (valid) {
        float s0 = p0 * 0.0625f;   // 1/sqrt(256)
        float s1 = p1 * 0.0625f;
        float m  = fmaxf(s0, s1);
        float e0 = expf(s0 - m);
        float e1 = expf(s1 - m);
        float inv = 1.f / (e0 + e1);
        a0 = e0 * inv;
        a1 = e1 * inv;
    } else {
        a0 = 1.f; a1 = 0.f;
    }
}

// full chain for row (b,l): returns the 8 lookback weights (lane 0 valid)
__device__ __forceinline__ void chain_w(const float* base, int l, int c8, float* w8)
{
    float al0[4], al1[4];
    float g0, d0, g1, d1;

    float o1[4][8];
    #pragma unroll
    for (int t = 0; t < 4; t++) {
        int lh = l - 2 * t;
        float xh[8], xl[8];
        load_row8(xh, base, lh, c8);
        load_row8(xl, base, lh - 1, c8);
        float p0, p1; dot2(xh, xl, p0, p1);
        float b0, b1; coef2(p0, p1, lh >= 1, b0, b1);
        al0[t] = b0; al1[t] = b1;
        #pragma unroll
        for (int k = 0; k < 8; k++)
            o1[t][k] = fmaf(b0, xh[k], fmaf(b1, xl[k], xh[k]));
    }
    float o2[2][8];
    #pragma unroll
    for (int t = 0; t < 2; t++) {
        int lh = l - 4 * t;
        float p0, p1; dot2(o1[2 * t], o1[2 * t + 1], p0, p1);
        float b0, b1; coef2(p0, p1, lh >= 2, b0, b1);
        if (t == 0) { g0 = b0; d0 = b1; }
        else        { g1 = b0; d1 = b1; }
        #pragma unroll
        for (int k = 0; k < 8; k++)
            o2[t][k] = fmaf(b0, o1[2 * t][k], fmaf(b1, o1[2 * t + 1][k], o1[2 * t][k]));
    }
    float e0, z0;
    {
        float p0, p1; dot2(o2[0], o2[1], p0, p1);
        coef2(p0, p1, l >= 4, e0, z0);
    }

    float eps = 1.f + e0, zet = z0;
    float G0 = 1.f + g0, D0v = d0, G1 = 1.f + g1, D1v = d1;
    w8[0] = eps * G0  * (1.f + al0[0]);
    w8[1] = eps * G0  * al1[0];
    w8[2] = eps * D0v * (1.f + al0[1]);
    w8[3] = eps * D0v * al1[1];
    w8[4] = zet * G1  * (1.f + al0[2]);
    w8[5] = zet * G1  * al1[2];
    w8[6] = zet * D1v * (1.f + al0[3]);
    w8[7] = zet * D1v * al1[3];
}

// =====================================================================
// Kernel A (s2, low prio): attn fill ONLY. One warp per (b,l).
// =====================================================================
__global__ void __launch_bounds__(256)
fill_kernel(const float* __restrict__ inp, float* __restrict__ attn_out)
{
    const int lane = threadIdx.x & 31;
    const int row  = blockIdx.x * 8 + (threadIdx.x >> 5);   // 0..16383
    const int b    = row >> 10;
    const int l    = row & (L_ - 1);
    const float* base = inp + (size_t)b * L_ * D_;
    const int c = lane * 8;

    float A0[NL_], A1[NL_];

    float o1[4][8];
    #pragma unroll
    for (int t = 0; t < 4; t++) {
        int lh = l - 2 * t;
        float xh[8], xl[8];
        load_row8(xh, base, lh, c);
        load_row8(xl, base, lh - 1, c);
        float p0, p1; dot2(xh, xl, p0, p1);
        float b0, b1; coef2(p0, p1, lh >= 1, b0, b1);
        #pragma unroll
        for (int k = 0; k < 8; k++)
            o1[t][k] = fmaf(b0, xh[k], fmaf(b1, xl[k], xh[k]));
        if (t == 0) { A0[0] = b0; A1[0] = b1; }
    }
    float o2[2][8];
    #pragma unroll
    for (int t = 0; t < 2; t++) {
        int lh = l - 4 * t;
        float p0, p1; dot2(o1[2 * t], o1[2 * t + 1], p0, p1);
        float b0, b1; coef2(p0, p1, lh >= 2, b0, b1);
        #pragma unroll
        for (int k = 0; k < 8; k++)
            o2[t][k] = fmaf(b0, o1[2 * t][k], fmaf(b1, o1[2 * t + 1][k], o1[2 * t][k]));
        if (t == 0) { A0[1] = b0; A1[1] = b1; }
    }
    {
        float p0, p1; dot2(o2[0], o2[1], p0, p1);
        float c0, c1; coef2(p0, p1, l >= 4, c0, c1);
        A0[2] = c0; A1[2] = c1;
    }

    #pragma unroll
    for (int layer = 0; layer < NL_; layer++) {
        const int d  = 1 << layer;
        const int c0 = l;
        const int c1 = l - d;
        const float a0 = A0[layer];
        const float a1 = A1[layer];
        float4* dst = (float4*)(attn_out + ((size_t)(b * NL_ + layer) * L_ + l) * L_);
        #pragma unroll
        for (int s = 0; s < 8; s++) {
            int q = lane + (s << 5);
            float4 v = make_float4(0.f, 0.f, 0.f, 0.f);
            if ((c0 >> 2) == q)              ((float*)&v)[c0 & 3] = a0;
            if (c1 >= 0 && (c1 >> 2) == q)   ((float*)&v)[c1 & 3] = a1;
            __stcs(dst + q, v);
        }
    }
}

// =====================================================================
// Kernel B (s3, high prio): P = inp @ W^T over all 16384 rows.
// (round-12 proven gemm, no epilogue extras)
// =====================================================================
#define GBM 128
#define GBN 128
#define GBK 32
#define SST 36

__global__ void __launch_bounds__(256, 2)
gemmP_kernel(const float* __restrict__ inp, const float* __restrict__ W)
{
    __shared__ unsigned As[GBM * SST];
    __shared__ unsigned Bs[GBN * SST];

    const int tid  = threadIdx.x;
    const int m0   = blockIdx.x * GBM;
    const int n0   = blockIdx.y * GBN;
    const int wid  = tid >> 5;
    const int lane = tid & 31;
    const int warp_m = wid & 3;
    const int warp_n = wid >> 2;
    const int gid = lane >> 2;
    const int tig = lane & 3;

    float acc[2][8][4];
    #pragma unroll
    for (int i = 0; i < 2; i++)
        #pragma unroll
        for (int j = 0; j < 8; j++)
            #pragma unroll
            for (int k = 0; k < 4; k++) acc[i][j][k] = 0.f;

    const float* aPtr[4];
    const float* bPtr[4];
    int sOff[4];
    #pragma unroll
    for (int it = 0; it < 4; it++) {
        int idx = tid + it * 256;
        int r   = idx >> 3;
        int q   = idx & 7;
        aPtr[it] = inp + (size_t)(m0 + r) * 256 + q * 4;
        bPtr[it] = W + (size_t)(n0 + r) * 256 + q * 4;
        sOff[it] = r * SST + q * 4;
    }

    float4 aR[4], bR[4];
    #pragma unroll
    for (int it = 0; it < 4; it++) {
        aR[it] = *(const float4*)(aPtr[it]);
        bR[it] = *(const float4*)(bPtr[it]);
    }

    #pragma unroll
    for (int i = 0; i < 8; i++) {
        const int kc = i * GBK;
        __syncthreads();
        #pragma unroll
        for (int it = 0; it < 4; it++) {
            *(uint4*)(As + sOff[it]) =
                make_uint4(f2tf32(aR[it].x), f2tf32(aR[it].y), f2tf32(aR[it].z), f2tf32(aR[it].w));
            *(uint4*)(Bs + sOff[it]) =
                make_uint4(f2tf32(bR[it].x), f2tf32(bR[it].y), f2tf32(bR[it].z), f2tf32(bR[it].w));
        }
        __syncthreads();

        if (i < 7) {
            #pragma unroll
            for (int it = 0; it < 4; it++) {
                aR[it] = *(const float4*)(aPtr[it] + kc + GBK);
                bR[it] = *(const float4*)(bPtr[it] + kc + GBK);
            }
        }

        #pragma unroll
        for (int kk = 0; kk < GBK; kk += 8) {
            unsigned a[2][4], bq[8][2];
            #pragma unroll
            for (int mt = 0; mt < 2; mt++) {
                int r = warp_m * 32 + mt * 16 + gid;
                a[mt][0] = As[r * SST + kk + tig];
                a[mt][1] = As[(r + 8) * SST + kk + tig];
                a[mt][2] = As[r * SST + kk + tig + 4];
                a[mt][3] = As[(r + 8) * SST + kk + tig + 4];
            }
            #pragma unroll
            for (int nt = 0; nt < 8; nt++) {
                int cix = warp_n * 64 + nt * 8 + gid;
                bq[nt][0] = Bs[cix * SST + kk + tig];
                bq[nt][1] = Bs[cix * SST + kk + tig + 4];
            }
            #pragma unroll
            for (int mt = 0; mt < 2; mt++)
                #pragma unroll
                for (int nt = 0; nt < 8; nt++)
                    mma_tf32(acc[mt][nt], a[mt], bq[nt]);
        }
    }

    #pragma unroll
    for (int mt = 0; mt < 2; mt++) {
        #pragma unroll
        for (int half = 0; half < 2; half++) {
            int m = m0 + warp_m * 32 + mt * 16 + gid + half * 8;
            float* prow = g_P + (size_t)m * 256;
            #pragma unroll
            for (int nt = 0; nt < 8; nt++) {
                int col = n0 + warp_n * 64 + nt * 8 + 2 * tig;
                *(float2*)(prow + col) =
                    make_float2(acc[mt][nt][half * 2 + 0], acc[mt][nt][half * 2 + 1]);
            }
        }
    }
}

// =====================================================================
// Kernel C (s3 after gemmP): computes its own w (smem), then
// o[b,l] = sum_j w_j(l) * P[b,l-j] + bias + residual.
// Block = 16 consecutive output rows (1008 % 16 == 0: no batch cross).
// =====================================================================
#define RPT 4

__global__ void __launch_bounds__(256)
combine_kernel(const float* __restrict__ inp, const float* __restrict__ bias,
               float* __restrict__ o_out)
{
    __shared__ float ws[16][8];

    const int tid  = threadIdx.x;
    const int wid  = tid >> 5;
    const int lane = tid & 31;

    const int mb0  = blockIdx.x * 16;        // first output row of block
    const int b    = mb0 / LQ_;
    const int lqb  = mb0 - b * LQ_;
    const float* base = inp + (size_t)b * L_ * D_;

    // ---- per-warp w chains: warp wid does block-rows wid and wid+8 ----
    {
        const int c8 = lane * 8;
        #pragma unroll
        for (int rr = 0; rr < 2; rr++) {
            const int r = wid + rr * 8;              // 0..15
            const int l = lqb + r + PAST_;
            float w8[8];
            chain_w(base, l, c8, w8);
            if (lane == 0) {
                #pragma unroll
                for (int j = 0; j < 8; j++) ws[r][j] = w8[j];
            }
        }
    }
    __syncthreads();

    // ---- combine main (round-9 proven register-window loop) ----
    const int grp  = tid >> 6;                // 0..3
    const int colq = tid & 63;
    const int col  = colq * 4;

    const int mb   = mb0 + grp * RPT;
    const int lq0  = lqb + grp * RPT;
    const int l0   = lq0 + PAST_;

    const float4 bi = *(const float4*)(bias + col);
    const float* pbase = g_P + ((size_t)b * L_) * 256 + col;
    const float* rbase = inp + ((size_t)b * L_ + l0) * D_ + (col & 63);
    float* obase = o_out + (size_t)mb * 256 + col;

    float4 p[8];
    #pragma unroll
    for (int i = 0; i < 8; i++)
        p[i] = *(const float4*)(pbase + (size_t)(l0 - 7 + i) * 256);

    #pragma unroll
    for (int r = 0; r < RPT; r++) {
        const float* wr = ws[grp * RPT + r];
        const float4 rv = *(const float4*)(rbase + (size_t)r * D_);

        float4 acc;
        acc.x = bi.x + rv.x; acc.y = bi.y + rv.y;
        acc.z = bi.z + rv.z; acc.w = bi.w + rv.w;
        #pragma unroll
        for (int j = 0; j < 8; j++) {
            const float wj = wr[j];
            const float4 pv = p[7 - j];
            acc.x = fmaf(wj, pv.x, acc.x);
            acc.y = fmaf(wj, pv.y, acc.y);
            acc.z = fmaf(wj, pv.z, acc.z);
            acc.w = fmaf(wj, pv.w, acc.w);
        }
        __stcs((float4*)(obase + (size_t)r * 256), acc);

        if (r < RPT - 1) {
            #pragma unroll
            for (int i = 0; i < 7; i++) p[i] = p[i + 1];
            p[7] = *(const float4*)(pbase + (size_t)(l0 + r + 1) * 256);
        }
    }
}

// =====================================================================
// launch: s3 (HIGH): gemmP -> combine ; s2 (LOW): fill.
// gemm recorded FIRST so its CTAs claim SM residency at replay.
// =====================================================================
static cudaStream_t g_s2 = 0, g_s3 = 0;
static cudaEvent_t  g_fork = 0, g_j2 = 0, g_j3 = 0;
static struct StreamInit {
    StreamInit() {
        int lo = 0, hi = 0;
        cudaDeviceGetStreamPriorityRange(&lo, &hi);
        cudaStreamCreateWithPriority(&g_s3, cudaStreamNonBlocking, hi);
        cudaStreamCreateWithPriority(&g_s2, cudaStreamNonBlocking, lo);
        cudaEventCreateWithFlags(&g_fork, cudaEventDisableTiming);
        cudaEventCreateWithFlags(&g_j2, cudaEventDisableTiming);
        cudaEventCreateWithFlags(&g_j3, cudaEventDisableTiming);
    }
} g_stream_init;

extern "C" void kernel_launch(void* const* d_in, const int* in_sizes, int n_in,
                              void* d_out, int out_size)
{
    const float* inp  = (const float*)d_in[0];
    const float* W    = (const float*)d_in[1];
    const float* bias = (const float*)d_in[2];
    // d_in[3] = masks : compile-time structure, unused

    float* out  = (float*)d_out;           // o : (16, 1008, 4, 64)
    float* attn = out + O_ELEMS;           // attn_stack : (16, 3, 1024, 1024)

    cudaEventRecord(g_fork, 0);
    cudaStreamWaitEvent(g_s3, g_fork, 0);
    cudaStreamWaitEvent(g_s2, g_fork, 0);

    gemmP_kernel<<<dim3((B_ * L_) / GBM, 256 / GBN), 256, 0, g_s3>>>(inp, W);
    fill_kernel<<<(B_ * L_) / 8, 256, 0, g_s2>>>(inp, attn);

    combine_kernel<<<(B_ * LQ_) / 16, 256, 0, g_s3>>>(inp, bias, out);

    cudaEventRecord(g_j2, g_s2);
    cudaEventRecord(g_j3, g_s3);
    cudaStreamWaitEvent(0, g_j2, 0);
    cudaStreamWaitEvent(0, g_j3, 0);
}